// round 13
// baseline (speedup 1.0000x reference)
#include <cuda_runtime.h>
#include <math.h>

#define NN 20000
#define EE 320000
#define HIDF 128

typedef unsigned long long u64;

#define PACK2(out, lo, hi) \
    asm("mov.b64 %0, {%1, %2};" : "=l"(out) : "f"(lo), "f"(hi))
#define UNPACK2(lo, hi, in) \
    asm("mov.b64 {%0, %1}, %2;" : "=f"(lo), "=f"(hi) : "l"(in))
#define FMA2(acc, a, b) \
    asm("fma.rn.f32x2 %0, %1, %2, %0;" : "+l"(acc) : "l"(a), "l"(b))

// ---------------- scratch (device globals; no allocation) ----------------
__device__ float g_hA[NN * HIDF];
__device__ float g_hB[NN * HIDF];
__device__ float g_PQ[NN * HIDF];
__device__ float g_agg[NN * HIDF];
__device__ float g_wpq[HIDF * HIDF];
__device__ float g_bpq[HIDF];

__device__ __forceinline__ int clamp_idx(int v) {
    v = v < 0 ? 0 : v;
    return v >= NN ? NN - 1 : v;
}

// ---------------- zero agg ----------------
__global__ void zero_agg_kernel() {
    int i = blockIdx.x * 256 + threadIdx.x;
    if (i < NN * HIDF) g_agg[i] = 0.0f;
}

// ---------------- repack conv W1 [256,64] -> [128,128] so PQ = h @ Wpq ----------------
__global__ void repack_w1_kernel(const float* __restrict__ w1, const float* __restrict__ b1) {
    int i = blockIdx.x;     // 0..127 input feature
    int j = threadIdx.x;    // 0..127 packed output
    float v = (j < 64) ? w1[i * 64 + j] : w1[(128 + i) * 64 + (j - 64)];
    g_wpq[i * 128 + j] = v;
    if (i == 0) g_bpq[j] = (j < 64) ? b1[j] : 0.0f;
}

// ---------------- tiled GEMM: C[M][BN] = A[M][128] @ W[128][BN] + bias ----------------
// BM=32, BK=32, 256 threads, f32x2 FMA, conflict-free LDS.
// Thread (tx,ty): rows ty*2..ty*2+1, cols { tx*4 + jv*64 }.
template <int BN>
__global__ __launch_bounds__(256) void gemm_kernel(const float* __restrict__ A,
                                                   const float* __restrict__ W,
                                                   const float* __restrict__ bias,
                                                   float* __restrict__ C, int M) {
    constexpr int NJ = BN / 64;               // 2 (BN=128) or 1 (BN=64)
    constexpr int WF4 = (32 * BN / 4) / 256;  // float4 W loads per thread: 4 or 2
    __shared__ __align__(16) float As[32][33];
    __shared__ __align__(16) float Ws[32][BN];

    const int tid = threadIdx.x;
    const int n0 = blockIdx.x * 32;
    const int tx = tid & 15;             // output column group
    const int ty = tid >> 4;             // row group (2 rows each)

    const int lrow = tid >> 3;           // 0..31 (A tile row)
    const int lcol = tid & 7;            // float4 slot within 32-wide k tile
    const int arow = min(n0 + lrow, M - 1);
    const float4* Arow = (const float4*)(A + (size_t)arow * 128);

    u64 acc[2][NJ * 2];
#pragma unroll
    for (int u = 0; u < 2; u++)
#pragma unroll
        for (int j = 0; j < NJ * 2; j++) acc[u][j] = 0ULL;

#pragma unroll 1
    for (int kt = 0; kt < 4; kt++) {
        float4 av = Arow[kt * 8 + lcol];
        float4 wreg[WF4];
#pragma unroll
        for (int i = 0; i < WF4; i++) {
            int idx = tid + i * 256;
            int wr = idx / (BN / 4);
            int wc = idx % (BN / 4);
            wreg[i] = ((const float4*)(W + (size_t)(kt * 32 + wr) * BN))[wc];
        }
        __syncthreads();
        As[lcol * 4 + 0][lrow] = av.x;
        As[lcol * 4 + 1][lrow] = av.y;
        As[lcol * 4 + 2][lrow] = av.z;
        As[lcol * 4 + 3][lrow] = av.w;
#pragma unroll
        for (int i = 0; i < WF4; i++) {
            int idx = tid + i * 256;
            int wr = idx / (BN / 4);
            int wc = idx % (BN / 4);
            ((float4*)&Ws[wr][0])[wc] = wreg[i];
        }
        __syncthreads();
#pragma unroll
        for (int kk = 0; kk < 32; kk++) {
            float a0 = As[kk][ty * 2 + 0];
            float a1 = As[kk][ty * 2 + 1];
            u64 pa0, pa1;
            PACK2(pa0, a0, a0);
            PACK2(pa1, a1, a1);
#pragma unroll
            for (int jv = 0; jv < NJ; jv++) {
                // lane tx reads element jv*16+tx -> consecutive lanes, consecutive 16B: no conflicts
                ulonglong2 w = ((const ulonglong2*)&Ws[kk][0])[jv * 16 + tx];
                FMA2(acc[0][jv * 2 + 0], pa0, w.x); FMA2(acc[0][jv * 2 + 1], pa0, w.y);
                FMA2(acc[1][jv * 2 + 0], pa1, w.x); FMA2(acc[1][jv * 2 + 1], pa1, w.y);
            }
        }
    }

    float bv[NJ * 4];
#pragma unroll
    for (int jv = 0; jv < NJ; jv++)
#pragma unroll
        for (int k = 0; k < 4; k++) bv[jv * 4 + k] = bias[jv * 64 + tx * 4 + k];
#pragma unroll
    for (int u = 0; u < 2; u++) {
        int row = n0 + ty * 2 + u;
        if (row < M) {
#pragma unroll
            for (int jv = 0; jv < NJ; jv++) {
                float v0, v1, v2, v3;
                UNPACK2(v0, v1, acc[u][jv * 2 + 0]);
                UNPACK2(v2, v3, acc[u][jv * 2 + 1]);
                *(float4*)(C + (size_t)row * BN + jv * 64 + tx * 4) =
                    make_float4(v0 + bv[jv * 4 + 0], v1 + bv[jv * 4 + 1],
                                v2 + bv[jv * 4 + 2], v3 + bv[jv * 4 + 3]);
            }
        }
    }
}

// ---------------- fused edge kernel ----------------
// Phase 1 (thread per edge): MLP2 (f32x2) + closed-form so(4) expm -> F in SHARED.
// Phase 2 (warp per edge x32, software-pipelined): projections + red.global.add.v4.
__global__ __launch_bounds__(256) void edge_fused_kernel(const float* __restrict__ h,
                                                         const int* __restrict__ ei,
                                                         const float* __restrict__ w2,
                                                         const float* __restrict__ b2) {
    __shared__ __align__(16) ulonglong2 w2s[512];   // [64 inputs][32 outputs]
    __shared__ __align__(16) u64 b2s[16];
    __shared__ __align__(16) float Fs[256 * 32];    // per local edge: f_u(16), f_v(16)
    __shared__ int rs[256], cs[256];

    for (int idx = threadIdx.x; idx < 512; idx += 256) w2s[idx] = ((const ulonglong2*)w2)[idx];
    if (threadIdx.x < 16) b2s[threadIdx.x] = ((const u64*)b2)[threadIdx.x];

    const int tid = threadIdx.x;
    const int e = blockIdx.x * 256 + tid;   // grid = EE/256
    const int r = clamp_idx(ei[e]);
    const int c = clamp_idx(ei[EE + e]);
    rs[tid] = r;
    cs[tid] = c;
    __syncthreads();

    // ---- phase 1: maps ----
    {
        const float4* Pr = (const float4*)(g_PQ + (size_t)r * 128);        // P = first 64
        const float4* Qr = (const float4*)(g_PQ + (size_t)c * 128 + 64);   // Q = last 64

        u64 mm[16];
#pragma unroll
        for (int j = 0; j < 16; j++) mm[j] = b2s[j];

#pragma unroll 4
        for (int i4 = 0; i4 < 16; i4++) {
            float4 p = Pr[i4], q = Qr[i4];
            float hv[4];
            hv[0] = fmaxf(p.x + q.x, 0.0f);
            hv[1] = fmaxf(p.y + q.y, 0.0f);
            hv[2] = fmaxf(p.z + q.z, 0.0f);
            hv[3] = fmaxf(p.w + q.w, 0.0f);
#pragma unroll
            for (int u = 0; u < 4; u++) {
                u64 ph;
                PACK2(ph, hv[u], hv[u]);
                const ulonglong2* wrow = &w2s[(i4 * 4 + u) * 8];
#pragma unroll
                for (int jv = 0; jv < 8; jv++) {
                    ulonglong2 w = wrow[jv];
                    FMA2(mm[jv * 2 + 0], ph, w.x);
                    FMA2(mm[jv * 2 + 1], ph, w.y);
                }
            }
        }

        float m[32];
#pragma unroll
        for (int j = 0; j < 16; j++) UNPACK2(m[2 * j], m[2 * j + 1], mm[j]);

#pragma unroll
        for (int side = 0; side < 2; side++) {
            const float* ms = &m[side * 16];
            float a12 = ms[1] - ms[4];
            float a13 = ms[2] - ms[8];
            float a14 = ms[3] - ms[12];
            float a23 = ms[6] - ms[9];
            float a24 = ms[7] - ms[13];
            float a34 = ms[11] - ms[14];

            float p1 = 0.5f * (a12 + a34), p2 = 0.5f * (a13 - a24), p3 = 0.5f * (a14 + a23);
            float q1 = 0.5f * (a12 - a34), q2 = 0.5f * (a13 + a24), q3 = 0.5f * (a14 - a23);

            float tp2 = p1 * p1 + p2 * p2 + p3 * p3;
            float tq2 = q1 * q1 + q2 * q2 + q3 * q3;
            float tp = sqrtf(tp2), tq = sqrtf(tq2);
            float svp, cvp, svq, cvq;
            __sincosf(tp, &svp, &cvp);
            __sincosf(tq, &svq, &cvq);
            float sp = (tp2 > 1e-12f) ? svp / tp : 1.0f - tp2 * (1.0f / 6.0f);
            float sq = (tq2 > 1e-12f) ? svq / tq : 1.0f - tq2 * (1.0f / 6.0f);

            float Ap[16] = {0.f,  p1,  p2,  p3,
                            -p1, 0.f,  p3, -p2,
                            -p2, -p3, 0.f,  p1,
                            -p3,  p2, -p1, 0.f};
            float Aq[16] = {0.f,  q1,  q2,  q3,
                            -q1, 0.f, -q3,  q2,
                            -q2,  q3, 0.f, -q1,
                            -q3, -q2,  q1, 0.f};
            float B[16];
#pragma unroll
            for (int a = 0; a < 4; a++)
#pragma unroll
                for (int b = 0; b < 4; b++)
                    B[a * 4 + b] = Ap[a * 4 + 0] * Aq[0 * 4 + b] + Ap[a * 4 + 1] * Aq[1 * 4 + b] +
                                   Ap[a * 4 + 2] * Aq[2 * 4 + b] + Ap[a * 4 + 3] * Aq[3 * 4 + b];

            float cc = cvp * cvq, scp = sp * cvq, csq = cvp * sq, ssv = sp * sq;
            float4* out = (float4*)(Fs + tid * 32 + side * 16);
#pragma unroll
            for (int rr = 0; rr < 4; rr++) {
                float t0 = ((4 * rr + 0) % 5 == 0 ? cc : 0.0f) + scp * Ap[rr * 4 + 0] + csq * Aq[rr * 4 + 0] + ssv * B[rr * 4 + 0];
                float t1 = ((4 * rr + 1) % 5 == 0 ? cc : 0.0f) + scp * Ap[rr * 4 + 1] + csq * Aq[rr * 4 + 1] + ssv * B[rr * 4 + 1];
                float t2 = ((4 * rr + 2) % 5 == 0 ? cc : 0.0f) + scp * Ap[rr * 4 + 2] + csq * Aq[rr * 4 + 2] + ssv * B[rr * 4 + 2];
                float t3 = ((4 * rr + 3) % 5 == 0 ? cc : 0.0f) + scp * Ap[rr * 4 + 3] + csq * Aq[rr * 4 + 3] + ssv * B[rr * 4 + 3];
                out[rr] = make_float4(t0, t1, t2, t3);
            }
        }
    }
    __syncthreads();

    // ---- phase 2: messages (warp per edge, pipelined: next gathers issue before red) ----
    const int warp = tid >> 5;
    const int lane = tid & 31;
    const int le0 = warp * 32;

    float4 xi = ((const float4*)(h + (size_t)cs[le0] * 128))[lane];
    float4 xj = ((const float4*)(h + (size_t)rs[le0] * 128))[lane];

#pragma unroll 1
    for (int i = 0; i < 32; i++) {
        int le = le0 + i;
        int cc = cs[le];

        float4 nxi, nxj;
        if (i < 31) {
            nxi = ((const float4*)(h + (size_t)cs[le + 1] * 128))[lane];
            nxj = ((const float4*)(h + (size_t)rs[le + 1] * 128))[lane];
        }

        const float4* Fp = (const float4*)(Fs + le * 32);
        float4 fu0 = Fp[0], fu1 = Fp[1], fu2 = Fp[2], fu3 = Fp[3];
        float4 fv0 = Fp[4], fv1 = Fp[5], fv2 = Fp[6], fv3 = Fp[7];

        float pi0 = fu0.x * xi.x + fu0.y * xi.y + fu0.z * xi.z + fu0.w * xi.w;
        float pi1 = fu1.x * xi.x + fu1.y * xi.y + fu1.z * xi.z + fu1.w * xi.w;
        float pi2 = fu2.x * xi.x + fu2.y * xi.y + fu2.z * xi.z + fu2.w * xi.w;
        float pi3 = fu3.x * xi.x + fu3.y * xi.y + fu3.z * xi.z + fu3.w * xi.w;
        float pj0 = fv0.x * xj.x + fv0.y * xj.y + fv0.z * xj.z + fv0.w * xj.w;
        float pj1 = fv1.x * xj.x + fv1.y * xj.y + fv1.z * xj.z + fv1.w * xj.w;
        float pj2 = fv2.x * xj.x + fv2.y * xj.y + fv2.z * xj.z + fv2.w * xj.w;
        float pj3 = fv3.x * xj.x + fv3.y * xj.y + fv3.z * xj.z + fv3.w * xj.w;

        float e0 = pi0 - pj0, e1 = pi1 - pj1, e2 = pi2 - pj2, e3 = pi3 - pj3;

        float m0 = fu0.x * e0 + fu1.x * e1 + fu2.x * e2 + fu3.x * e3;
        float m1 = fu0.y * e0 + fu1.y * e1 + fu2.y * e2 + fu3.y * e3;
        float m2 = fu0.z * e0 + fu1.z * e1 + fu2.z * e2 + fu3.z * e3;
        float m3 = fu0.w * e0 + fu1.w * e1 + fu2.w * e2 + fu3.w * e3;

        float* dst = g_agg + (size_t)cc * 128 + lane * 4;   // 16B aligned
        asm volatile("red.global.add.v4.f32 [%0], {%1, %2, %3, %4};"
                     :: "l"(dst), "f"(m0), "f"(m1), "f"(m2), "f"(m3) : "memory");

        xi = nxi;
        xj = nxj;
    }
}

// ---------------- update: hout = elu(hin - eps*agg), re-zero agg ----------------
__global__ void update_elu_kernel(const float* __restrict__ hin, float* __restrict__ hout,
                                  const float* __restrict__ eps) {
    int i = blockIdx.x * 256 + threadIdx.x;
    if (i >= NN * HIDF) return;
    float v = hin[i] - eps[0] * g_agg[i];
    hout[i] = (v > 0.0f) ? v : expm1f(v);
    g_agg[i] = 0.0f;
}

// ---------------- launch ----------------
extern "C" void kernel_launch(void* const* d_in, const int* in_sizes, int n_in,
                              void* d_out, int out_size) {
    const float* x         = (const float*)d_in[0];
    const int* ei          = (const int*)d_in[1];
    const float* lin_in_w  = (const float*)d_in[2];
    const float* lin_in_b  = (const float*)d_in[3];
    const float* c0_w1     = (const float*)d_in[4];
    const float* c0_b1     = (const float*)d_in[5];
    const float* c0_w2     = (const float*)d_in[6];
    const float* c0_b2     = (const float*)d_in[7];
    const float* c0_eps    = (const float*)d_in[8];
    const float* c1_w1     = (const float*)d_in[9];
    const float* c1_b1     = (const float*)d_in[10];
    const float* c1_w2     = (const float*)d_in[11];
    const float* c1_b2     = (const float*)d_in[12];
    const float* c1_eps    = (const float*)d_in[13];
    const float* lin_out_w = (const float*)d_in[14];
    const float* lin_out_b = (const float*)d_in[15];
    float* out = (float*)d_out;

    float* hA;  cudaGetSymbolAddress((void**)&hA, g_hA);
    float* hB;  cudaGetSymbolAddress((void**)&hB, g_hB);
    float* PQ;  cudaGetSymbolAddress((void**)&PQ, g_PQ);
    float* wpq; cudaGetSymbolAddress((void**)&wpq, g_wpq);
    float* bpq; cudaGetSymbolAddress((void**)&bpq, g_bpq);

    const int gemmBlocks = (NN + 31) / 32;     // 625
    const int edgeBlocks = EE / 256;           // 1250
    const int elemBlocks = (NN * HIDF) / 256;  // 10000

    zero_agg_kernel<<<elemBlocks, 256>>>();

    // h = x @ Win + b
    gemm_kernel<128><<<gemmBlocks, 256>>>(x, lin_in_w, lin_in_b, hA, NN);

    // ---- conv0: hA -> hB ----
    repack_w1_kernel<<<128, 128>>>(c0_w1, c0_b1);
    gemm_kernel<128><<<gemmBlocks, 256>>>(hA, wpq, bpq, PQ, NN);
    edge_fused_kernel<<<edgeBlocks, 256>>>(hA, ei, c0_w2, c0_b2);
    update_elu_kernel<<<elemBlocks, 256>>>(hA, hB, c0_eps);

    // ---- conv1: hB -> hA ----
    repack_w1_kernel<<<128, 128>>>(c1_w1, c1_b1);
    gemm_kernel<128><<<gemmBlocks, 256>>>(hB, wpq, bpq, PQ, NN);
    edge_fused_kernel<<<edgeBlocks, 256>>>(hB, ei, c1_w2, c1_b2);
    update_elu_kernel<<<elemBlocks, 256>>>(hB, hA, c1_eps);

    // out = hA @ Wout + bout
    gemm_kernel<64><<<gemmBlocks, 256>>>(hA, lin_out_w, lin_out_b, out, NN);
}

// round 14
// speedup vs baseline: 1.0960x; 1.0960x over previous
#include <cuda_runtime.h>
#include <math.h>

#define NN 20000
#define EE 320000
#define HIDF 128

typedef unsigned long long u64;

#define PACK2(out, lo, hi) \
    asm("mov.b64 %0, {%1, %2};" : "=l"(out) : "f"(lo), "f"(hi))
#define UNPACK2(lo, hi, in) \
    asm("mov.b64 {%0, %1}, %2;" : "=f"(lo), "=f"(hi) : "l"(in))
#define FMA2(acc, a, b) \
    asm("fma.rn.f32x2 %0, %1, %2, %0;" : "+l"(acc) : "l"(a), "l"(b))

// ---------------- scratch (device globals; no allocation) ----------------
__device__ float g_hA[NN * HIDF];
__device__ float g_hB[NN * HIDF];
__device__ float g_PQ[NN * HIDF];
__device__ float g_agg[NN * HIDF];
__device__ float g_wpq[HIDF * HIDF];
__device__ float g_bpq[HIDF];

__device__ __forceinline__ int clamp_idx(int v) {
    v = v < 0 ? 0 : v;
    return v >= NN ? NN - 1 : v;
}

// ---------------- zero agg (float4) ----------------
__global__ void zero_agg_kernel() {
    int i = blockIdx.x * 256 + threadIdx.x;
    if (i < NN * HIDF / 4) ((float4*)g_agg)[i] = make_float4(0.f, 0.f, 0.f, 0.f);
}

// ---------------- repack conv W1 [256,64] -> [128,128] so PQ = h @ Wpq ----------------
__global__ void repack_w1_kernel(const float* __restrict__ w1, const float* __restrict__ b1) {
    int i = blockIdx.x;     // 0..127 input feature
    int j = threadIdx.x;    // 0..127 packed output
    float v = (j < 64) ? w1[i * 64 + j] : w1[(128 + i) * 64 + (j - 64)];
    g_wpq[i * 128 + j] = v;
    if (i == 0) g_bpq[j] = (j < 64) ? b1[j] : 0.0f;
}

// ---------------- tiled GEMM: C[M][BN] = A[M][128] @ W[128][BN] + bias ----------------
// BM=64, BK=16, 256 threads, f32x2 FMA, conflict-free LDS, double-buffered smem.
// Thread (tx,ty): rows ty*4..ty*4+3, cols { tx*4 + jv*64 }.
template <int BN>
__global__ __launch_bounds__(256) void gemm_kernel(const float* __restrict__ A,
                                                   const float* __restrict__ W,
                                                   const float* __restrict__ bias,
                                                   float* __restrict__ C, int M) {
    constexpr int NJ = BN / 64;               // 2 (BN=128) or 1 (BN=64)
    constexpr int WF4 = (16 * BN / 4) / 256;  // float4 W loads per thread: 2 or 1
    __shared__ __align__(16) float As[2][16][65];
    __shared__ __align__(16) float Ws[2][16][BN];

    const int tid = threadIdx.x;
    const int n0 = blockIdx.x * 64;
    const int tx = tid & 15;             // output column group
    const int ty = tid >> 4;             // row group (4 rows each)

    const int lrow = tid >> 2;           // 0..63 (A tile row)
    const int lcol = tid & 3;            // float4 slot within 16-wide k tile
    const int arow = min(n0 + lrow, M - 1);
    const float4* Arow = (const float4*)(A + (size_t)arow * 128);

    u64 acc[4][NJ * 2];
#pragma unroll
    for (int u = 0; u < 4; u++)
#pragma unroll
        for (int j = 0; j < NJ * 2; j++) acc[u][j] = 0ULL;

    // prologue: load tile 0
    float4 av = Arow[lcol];
    float4 wreg[WF4];
#pragma unroll
    for (int i = 0; i < WF4; i++) {
        int idx = tid + i * 256;
        int wr = idx / (BN / 4);
        int wc = idx % (BN / 4);
        wreg[i] = ((const float4*)(W + (size_t)wr * BN))[wc];
    }
    {
        As[0][lcol * 4 + 0][lrow] = av.x;
        As[0][lcol * 4 + 1][lrow] = av.y;
        As[0][lcol * 4 + 2][lrow] = av.z;
        As[0][lcol * 4 + 3][lrow] = av.w;
#pragma unroll
        for (int i = 0; i < WF4; i++) {
            int idx = tid + i * 256;
            int wr = idx / (BN / 4);
            int wc = idx % (BN / 4);
            ((float4*)&Ws[0][wr][0])[wc] = wreg[i];
        }
    }
    __syncthreads();

#pragma unroll 1
    for (int kt = 0; kt < 8; kt++) {
        const int cur = kt & 1;
        // issue next-tile GMEM loads before computing current tile
        if (kt < 7) {
            av = Arow[(kt + 1) * 4 + lcol];
#pragma unroll
            for (int i = 0; i < WF4; i++) {
                int idx = tid + i * 256;
                int wr = idx / (BN / 4);
                int wc = idx % (BN / 4);
                wreg[i] = ((const float4*)(W + (size_t)((kt + 1) * 16 + wr) * BN))[wc];
            }
        }
#pragma unroll
        for (int kk = 0; kk < 16; kk++) {
            float a0 = As[cur][kk][ty * 4 + 0];
            float a1 = As[cur][kk][ty * 4 + 1];
            float a2 = As[cur][kk][ty * 4 + 2];
            float a3 = As[cur][kk][ty * 4 + 3];
            u64 pa0, pa1, pa2, pa3;
            PACK2(pa0, a0, a0);
            PACK2(pa1, a1, a1);
            PACK2(pa2, a2, a2);
            PACK2(pa3, a3, a3);
#pragma unroll
            for (int jv = 0; jv < NJ; jv++) {
                // lane tx reads element jv*16+tx -> consecutive lanes, consecutive 16B: no conflicts
                ulonglong2 w = ((const ulonglong2*)&Ws[cur][kk][0])[jv * 16 + tx];
                FMA2(acc[0][jv * 2 + 0], pa0, w.x); FMA2(acc[0][jv * 2 + 1], pa0, w.y);
                FMA2(acc[1][jv * 2 + 0], pa1, w.x); FMA2(acc[1][jv * 2 + 1], pa1, w.y);
                FMA2(acc[2][jv * 2 + 0], pa2, w.x); FMA2(acc[2][jv * 2 + 1], pa2, w.y);
                FMA2(acc[3][jv * 2 + 0], pa3, w.x); FMA2(acc[3][jv * 2 + 1], pa3, w.y);
            }
        }
        if (kt < 7) {
            const int nxt = cur ^ 1;
            __syncthreads();
            As[nxt][lcol * 4 + 0][lrow] = av.x;
            As[nxt][lcol * 4 + 1][lrow] = av.y;
            As[nxt][lcol * 4 + 2][lrow] = av.z;
            As[nxt][lcol * 4 + 3][lrow] = av.w;
#pragma unroll
            for (int i = 0; i < WF4; i++) {
                int idx = tid + i * 256;
                int wr = idx / (BN / 4);
                int wc = idx % (BN / 4);
                ((float4*)&Ws[nxt][wr][0])[wc] = wreg[i];
            }
            __syncthreads();
        }
    }

    float bv[NJ * 4];
#pragma unroll
    for (int jv = 0; jv < NJ; jv++)
#pragma unroll
        for (int k = 0; k < 4; k++) bv[jv * 4 + k] = bias[jv * 64 + tx * 4 + k];
#pragma unroll
    for (int u = 0; u < 4; u++) {
        int row = n0 + ty * 4 + u;
        if (row < M) {
#pragma unroll
            for (int jv = 0; jv < NJ; jv++) {
                float v0, v1, v2, v3;
                UNPACK2(v0, v1, acc[u][jv * 2 + 0]);
                UNPACK2(v2, v3, acc[u][jv * 2 + 1]);
                *(float4*)(C + (size_t)row * BN + jv * 64 + tx * 4) =
                    make_float4(v0 + bv[jv * 4 + 0], v1 + bv[jv * 4 + 1],
                                v2 + bv[jv * 4 + 2], v3 + bv[jv * 4 + 3]);
            }
        }
    }
}

// ---------------- fused edge kernel ----------------
// Phase 1 (thread per edge): MLP2 (f32x2) + closed-form so(4) expm -> F in SHARED.
// Phase 2 (warp per edge x32, software-pipelined): projections + red.global.add.v4.
__global__ __launch_bounds__(256) void edge_fused_kernel(const float* __restrict__ h,
                                                         const int* __restrict__ ei,
                                                         const float* __restrict__ w2,
                                                         const float* __restrict__ b2) {
    __shared__ __align__(16) ulonglong2 w2s[512];   // [64 inputs][32 outputs]
    __shared__ __align__(16) u64 b2s[16];
    __shared__ __align__(16) float Fs[256 * 32];    // per local edge: f_u(16), f_v(16)
    __shared__ int rs[256], cs[256];

    for (int idx = threadIdx.x; idx < 512; idx += 256) w2s[idx] = ((const ulonglong2*)w2)[idx];
    if (threadIdx.x < 16) b2s[threadIdx.x] = ((const u64*)b2)[threadIdx.x];

    const int tid = threadIdx.x;
    const int e = blockIdx.x * 256 + tid;   // grid = EE/256
    const int r = clamp_idx(ei[e]);
    const int c = clamp_idx(ei[EE + e]);
    rs[tid] = r;
    cs[tid] = c;
    __syncthreads();

    // ---- phase 1: maps ----
    {
        const float4* Pr = (const float4*)(g_PQ + (size_t)r * 128);        // P = first 64
        const float4* Qr = (const float4*)(g_PQ + (size_t)c * 128 + 64);   // Q = last 64

        u64 mm[16];
#pragma unroll
        for (int j = 0; j < 16; j++) mm[j] = b2s[j];

#pragma unroll 4
        for (int i4 = 0; i4 < 16; i4++) {
            float4 p = Pr[i4], q = Qr[i4];
            float hv[4];
            hv[0] = fmaxf(p.x + q.x, 0.0f);
            hv[1] = fmaxf(p.y + q.y, 0.0f);
            hv[2] = fmaxf(p.z + q.z, 0.0f);
            hv[3] = fmaxf(p.w + q.w, 0.0f);
#pragma unroll
            for (int u = 0; u < 4; u++) {
                u64 ph;
                PACK2(ph, hv[u], hv[u]);
                const ulonglong2* wrow = &w2s[(i4 * 4 + u) * 8];
#pragma unroll
                for (int jv = 0; jv < 8; jv++) {
                    ulonglong2 w = wrow[jv];
                    FMA2(mm[jv * 2 + 0], ph, w.x);
                    FMA2(mm[jv * 2 + 1], ph, w.y);
                }
            }
        }

        float m[32];
#pragma unroll
        for (int j = 0; j < 16; j++) UNPACK2(m[2 * j], m[2 * j + 1], mm[j]);

#pragma unroll
        for (int side = 0; side < 2; side++) {
            const float* ms = &m[side * 16];
            float a12 = ms[1] - ms[4];
            float a13 = ms[2] - ms[8];
            float a14 = ms[3] - ms[12];
            float a23 = ms[6] - ms[9];
            float a24 = ms[7] - ms[13];
            float a34 = ms[11] - ms[14];

            float p1 = 0.5f * (a12 + a34), p2 = 0.5f * (a13 - a24), p3 = 0.5f * (a14 + a23);
            float q1 = 0.5f * (a12 - a34), q2 = 0.5f * (a13 + a24), q3 = 0.5f * (a14 - a23);

            float tp2 = p1 * p1 + p2 * p2 + p3 * p3;
            float tq2 = q1 * q1 + q2 * q2 + q3 * q3;
            float tp = sqrtf(tp2), tq = sqrtf(tq2);
            float svp, cvp, svq, cvq;
            __sincosf(tp, &svp, &cvp);
            __sincosf(tq, &svq, &cvq);
            float sp = (tp2 > 1e-12f) ? svp / tp : 1.0f - tp2 * (1.0f / 6.0f);
            float sq = (tq2 > 1e-12f) ? svq / tq : 1.0f - tq2 * (1.0f / 6.0f);

            float Ap[16] = {0.f,  p1,  p2,  p3,
                            -p1, 0.f,  p3, -p2,
                            -p2, -p3, 0.f,  p1,
                            -p3,  p2, -p1, 0.f};
            float Aq[16] = {0.f,  q1,  q2,  q3,
                            -q1, 0.f, -q3,  q2,
                            -q2,  q3, 0.f, -q1,
                            -q3, -q2,  q1, 0.f};
            float B[16];
#pragma unroll
            for (int a = 0; a < 4; a++)
#pragma unroll
                for (int b = 0; b < 4; b++)
                    B[a * 4 + b] = Ap[a * 4 + 0] * Aq[0 * 4 + b] + Ap[a * 4 + 1] * Aq[1 * 4 + b] +
                                   Ap[a * 4 + 2] * Aq[2 * 4 + b] + Ap[a * 4 + 3] * Aq[3 * 4 + b];

            float cc = cvp * cvq, scp = sp * cvq, csq = cvp * sq, ssv = sp * sq;
            float4* out = (float4*)(Fs + tid * 32 + side * 16);
#pragma unroll
            for (int rr = 0; rr < 4; rr++) {
                float t0 = ((4 * rr + 0) % 5 == 0 ? cc : 0.0f) + scp * Ap[rr * 4 + 0] + csq * Aq[rr * 4 + 0] + ssv * B[rr * 4 + 0];
                float t1 = ((4 * rr + 1) % 5 == 0 ? cc : 0.0f) + scp * Ap[rr * 4 + 1] + csq * Aq[rr * 4 + 1] + ssv * B[rr * 4 + 1];
                float t2 = ((4 * rr + 2) % 5 == 0 ? cc : 0.0f) + scp * Ap[rr * 4 + 2] + csq * Aq[rr * 4 + 2] + ssv * B[rr * 4 + 2];
                float t3 = ((4 * rr + 3) % 5 == 0 ? cc : 0.0f) + scp * Ap[rr * 4 + 3] + csq * Aq[rr * 4 + 3] + ssv * B[rr * 4 + 3];
                out[rr] = make_float4(t0, t1, t2, t3);
            }
        }
    }
    __syncthreads();

    // ---- phase 2: messages (warp per edge, pipelined: next gathers issue before red) ----
    const int warp = tid >> 5;
    const int lane = tid & 31;
    const int le0 = warp * 32;

    float4 xi = ((const float4*)(h + (size_t)cs[le0] * 128))[lane];
    float4 xj = ((const float4*)(h + (size_t)rs[le0] * 128))[lane];

#pragma unroll 1
    for (int i = 0; i < 32; i++) {
        int le = le0 + i;
        int cc = cs[le];

        float4 nxi, nxj;
        if (i < 31) {
            nxi = ((const float4*)(h + (size_t)cs[le + 1] * 128))[lane];
            nxj = ((const float4*)(h + (size_t)rs[le + 1] * 128))[lane];
        }

        const float4* Fp = (const float4*)(Fs + le * 32);
        float4 fu0 = Fp[0], fu1 = Fp[1], fu2 = Fp[2], fu3 = Fp[3];
        float4 fv0 = Fp[4], fv1 = Fp[5], fv2 = Fp[6], fv3 = Fp[7];

        float pi0 = fu0.x * xi.x + fu0.y * xi.y + fu0.z * xi.z + fu0.w * xi.w;
        float pi1 = fu1.x * xi.x + fu1.y * xi.y + fu1.z * xi.z + fu1.w * xi.w;
        float pi2 = fu2.x * xi.x + fu2.y * xi.y + fu2.z * xi.z + fu2.w * xi.w;
        float pi3 = fu3.x * xi.x + fu3.y * xi.y + fu3.z * xi.z + fu3.w * xi.w;
        float pj0 = fv0.x * xj.x + fv0.y * xj.y + fv0.z * xj.z + fv0.w * xj.w;
        float pj1 = fv1.x * xj.x + fv1.y * xj.y + fv1.z * xj.z + fv1.w * xj.w;
        float pj2 = fv2.x * xj.x + fv2.y * xj.y + fv2.z * xj.z + fv2.w * xj.w;
        float pj3 = fv3.x * xj.x + fv3.y * xj.y + fv3.z * xj.z + fv3.w * xj.w;

        float e0 = pi0 - pj0, e1 = pi1 - pj1, e2 = pi2 - pj2, e3 = pi3 - pj3;

        float m0 = fu0.x * e0 + fu1.x * e1 + fu2.x * e2 + fu3.x * e3;
        float m1 = fu0.y * e0 + fu1.y * e1 + fu2.y * e2 + fu3.y * e3;
        float m2 = fu0.z * e0 + fu1.z * e1 + fu2.z * e2 + fu3.z * e3;
        float m3 = fu0.w * e0 + fu1.w * e1 + fu2.w * e2 + fu3.w * e3;

        float* dst = g_agg + (size_t)cc * 128 + lane * 4;   // 16B aligned
        asm volatile("red.global.add.v4.f32 [%0], {%1, %2, %3, %4};"
                     :: "l"(dst), "f"(m0), "f"(m1), "f"(m2), "f"(m3) : "memory");

        xi = nxi;
        xj = nxj;
    }
}

// ---------------- update: hout = elu(hin - eps*agg), re-zero agg (float4) ----------------
__global__ void update_elu_kernel(const float4* __restrict__ hin, float4* __restrict__ hout,
                                  const float* __restrict__ eps) {
    int i = blockIdx.x * 256 + threadIdx.x;
    if (i >= NN * HIDF / 4) return;
    float ev = eps[0];
    float4 a = ((const float4*)g_agg)[i];
    float4 hv = hin[i];
    float4 o;
    float v;
    v = hv.x - ev * a.x; o.x = (v > 0.0f) ? v : expm1f(v);
    v = hv.y - ev * a.y; o.y = (v > 0.0f) ? v : expm1f(v);
    v = hv.z - ev * a.z; o.z = (v > 0.0f) ? v : expm1f(v);
    v = hv.w - ev * a.w; o.w = (v > 0.0f) ? v : expm1f(v);
    hout[i] = o;
    ((float4*)g_agg)[i] = make_float4(0.f, 0.f, 0.f, 0.f);
}

// ---------------- launch ----------------
extern "C" void kernel_launch(void* const* d_in, const int* in_sizes, int n_in,
                              void* d_out, int out_size) {
    const float* x         = (const float*)d_in[0];
    const int* ei          = (const int*)d_in[1];
    const float* lin_in_w  = (const float*)d_in[2];
    const float* lin_in_b  = (const float*)d_in[3];
    const float* c0_w1     = (const float*)d_in[4];
    const float* c0_b1     = (const float*)d_in[5];
    const float* c0_w2     = (const float*)d_in[6];
    const float* c0_b2     = (const float*)d_in[7];
    const float* c0_eps    = (const float*)d_in[8];
    const float* c1_w1     = (const float*)d_in[9];
    const float* c1_b1     = (const float*)d_in[10];
    const float* c1_w2     = (const float*)d_in[11];
    const float* c1_b2     = (const float*)d_in[12];
    const float* c1_eps    = (const float*)d_in[13];
    const float* lin_out_w = (const float*)d_in[14];
    const float* lin_out_b = (const float*)d_in[15];
    float* out = (float*)d_out;

    float* hA;  cudaGetSymbolAddress((void**)&hA, g_hA);
    float* hB;  cudaGetSymbolAddress((void**)&hB, g_hB);
    float* PQ;  cudaGetSymbolAddress((void**)&PQ, g_PQ);
    float* wpq; cudaGetSymbolAddress((void**)&wpq, g_wpq);
    float* bpq; cudaGetSymbolAddress((void**)&bpq, g_bpq);

    const int gemmBlocks = (NN + 63) / 64;         // 313
    const int edgeBlocks = EE / 256;               // 1250
    const int vecBlocks  = (NN * HIDF / 4) / 256;  // 2500

    zero_agg_kernel<<<vecBlocks, 256>>>();

    // h = x @ Win + b
    gemm_kernel<128><<<gemmBlocks, 256>>>(x, lin_in_w, lin_in_b, hA, NN);

    // ---- conv0: hA -> hB ----
    repack_w1_kernel<<<128, 128>>>(c0_w1, c0_b1);
    gemm_kernel<128><<<gemmBlocks, 256>>>(hA, wpq, bpq, PQ, NN);
    edge_fused_kernel<<<edgeBlocks, 256>>>(hA, ei, c0_w2, c0_b2);
    update_elu_kernel<<<vecBlocks, 256>>>((const float4*)hA, (float4*)hB, c0_eps);

    // ---- conv1: hB -> hA ----
    repack_w1_kernel<<<128, 128>>>(c1_w1, c1_b1);
    gemm_kernel<128><<<gemmBlocks, 256>>>(hB, wpq, bpq, PQ, NN);
    edge_fused_kernel<<<edgeBlocks, 256>>>(hB, ei, c1_w2, c1_b2);
    update_elu_kernel<<<vecBlocks, 256>>>((const float4*)hB, (float4*)hA, c1_eps);

    // out = hA @ Wout + bout
    gemm_kernel<64><<<gemmBlocks, 256>>>(hA, lin_out_w, lin_out_b, out, NN);
}

// round 16
// speedup vs baseline: 1.2219x; 1.1149x over previous
#include <cuda_runtime.h>
#include <math.h>

#define NN 20000
#define EE 320000
#define HIDF 128

typedef unsigned long long u64;

#define PACK2(out, lo, hi) \
    asm("mov.b64 %0, {%1, %2};" : "=l"(out) : "f"(lo), "f"(hi))
#define UNPACK2(lo, hi, in) \
    asm("mov.b64 {%0, %1}, %2;" : "=f"(lo), "=f"(hi) : "l"(in))
#define FMA2(acc, a, b) \
    asm("fma.rn.f32x2 %0, %1, %2, %0;" : "+l"(acc) : "l"(a), "l"(b))

// ---------------- scratch (device globals; no allocation) ----------------
__device__ float g_hA[NN * HIDF];
__device__ float g_hB[NN * HIDF];
__device__ float g_PQ[NN * HIDF];
__device__ float g_agg[NN * HIDF];
__device__ float g_deg[NN];
__device__ float g_wpq[HIDF * HIDF];
__device__ float g_bpq[HIDF];

__device__ __forceinline__ int clamp_idx(int v) {
    v = v < 0 ? 0 : v;
    return v >= NN ? NN - 1 : v;
}

// ---------------- zero agg + deg (float4) ----------------
__global__ void zero_agg_kernel() {
    int i = blockIdx.x * 256 + threadIdx.x;
    if (i < NN * HIDF / 4) ((float4*)g_agg)[i] = make_float4(0.f, 0.f, 0.f, 0.f);
    if (i < NN) g_deg[i] = 0.0f;
}

// ---------------- degree count (col side) ----------------
__global__ void deg_kernel(const int* __restrict__ ei) {
    int e = blockIdx.x * 256 + threadIdx.x;
    if (e < EE) {
        int c = clamp_idx(ei[EE + e]);
        atomicAdd(&g_deg[c], 1.0f);
    }
}

// ---------------- repack conv W1 [256,64] -> [128,128] so PQ = h @ Wpq ----------------
__global__ void repack_w1_kernel(const float* __restrict__ w1, const float* __restrict__ b1) {
    int i = blockIdx.x;     // 0..127 input feature
    int j = threadIdx.x;    // 0..127 packed output
    float v = (j < 64) ? w1[i * 64 + j] : w1[(128 + i) * 64 + (j - 64)];
    g_wpq[i * 128 + j] = v;
    if (i == 0) g_bpq[j] = (j < 64) ? b1[j] : 0.0f;
}

// ---------------- tiled GEMM: C[M][BN] = A[M][128] @ W[128][BN] + bias ----------------
// BM=64, BK=16, 256 threads, f32x2 FMA, conflict-free LDS, double-buffered smem.
template <int BN>
__global__ __launch_bounds__(256) void gemm_kernel(const float* __restrict__ A,
                                                   const float* __restrict__ W,
                                                   const float* __restrict__ bias,
                                                   float* __restrict__ C, int M) {
    constexpr int NJ = BN / 64;               // 2 (BN=128) or 1 (BN=64)
    constexpr int WF4 = (16 * BN / 4) / 256;  // float4 W loads per thread: 2 or 1
    __shared__ __align__(16) float As[2][16][65];
    __shared__ __align__(16) float Ws[2][16][BN];

    const int tid = threadIdx.x;
    const int n0 = blockIdx.x * 64;
    const int tx = tid & 15;             // output column group
    const int ty = tid >> 4;             // row group (4 rows each)

    const int lrow = tid >> 2;           // 0..63 (A tile row)
    const int lcol = tid & 3;            // float4 slot within 16-wide k tile
    const int arow = min(n0 + lrow, M - 1);
    const float4* Arow = (const float4*)(A + (size_t)arow * 128);

    u64 acc[4][NJ * 2];
#pragma unroll
    for (int u = 0; u < 4; u++)
#pragma unroll
        for (int j = 0; j < NJ * 2; j++) acc[u][j] = 0ULL;

    // prologue: load tile 0
    float4 av = Arow[lcol];
    float4 wreg[WF4];
#pragma unroll
    for (int i = 0; i < WF4; i++) {
        int idx = tid + i * 256;
        int wr = idx / (BN / 4);
        int wc = idx % (BN / 4);
        wreg[i] = ((const float4*)(W + (size_t)wr * BN))[wc];
    }
    {
        As[0][lcol * 4 + 0][lrow] = av.x;
        As[0][lcol * 4 + 1][lrow] = av.y;
        As[0][lcol * 4 + 2][lrow] = av.z;
        As[0][lcol * 4 + 3][lrow] = av.w;
#pragma unroll
        for (int i = 0; i < WF4; i++) {
            int idx = tid + i * 256;
            int wr = idx / (BN / 4);
            int wc = idx % (BN / 4);
            ((float4*)&Ws[0][wr][0])[wc] = wreg[i];
        }
    }
    __syncthreads();

#pragma unroll 1
    for (int kt = 0; kt < 8; kt++) {
        const int cur = kt & 1;
        if (kt < 7) {
            av = Arow[(kt + 1) * 4 + lcol];
#pragma unroll
            for (int i = 0; i < WF4; i++) {
                int idx = tid + i * 256;
                int wr = idx / (BN / 4);
                int wc = idx % (BN / 4);
                wreg[i] = ((const float4*)(W + (size_t)((kt + 1) * 16 + wr) * BN))[wc];
            }
        }
#pragma unroll
        for (int kk = 0; kk < 16; kk++) {
            float a0 = As[cur][kk][ty * 4 + 0];
            float a1 = As[cur][kk][ty * 4 + 1];
            float a2 = As[cur][kk][ty * 4 + 2];
            float a3 = As[cur][kk][ty * 4 + 3];
            u64 pa0, pa1, pa2, pa3;
            PACK2(pa0, a0, a0);
            PACK2(pa1, a1, a1);
            PACK2(pa2, a2, a2);
            PACK2(pa3, a3, a3);
#pragma unroll
            for (int jv = 0; jv < NJ; jv++) {
                ulonglong2 w = ((const ulonglong2*)&Ws[cur][kk][0])[jv * 16 + tx];
                FMA2(acc[0][jv * 2 + 0], pa0, w.x); FMA2(acc[0][jv * 2 + 1], pa0, w.y);
                FMA2(acc[1][jv * 2 + 0], pa1, w.x); FMA2(acc[1][jv * 2 + 1], pa1, w.y);
                FMA2(acc[2][jv * 2 + 0], pa2, w.x); FMA2(acc[2][jv * 2 + 1], pa2, w.y);
                FMA2(acc[3][jv * 2 + 0], pa3, w.x); FMA2(acc[3][jv * 2 + 1], pa3, w.y);
            }
        }
        if (kt < 7) {
            const int nxt = cur ^ 1;
            __syncthreads();
            As[nxt][lcol * 4 + 0][lrow] = av.x;
            As[nxt][lcol * 4 + 1][lrow] = av.y;
            As[nxt][lcol * 4 + 2][lrow] = av.z;
            As[nxt][lcol * 4 + 3][lrow] = av.w;
#pragma unroll
            for (int i = 0; i < WF4; i++) {
                int idx = tid + i * 256;
                int wr = idx / (BN / 4);
                int wc = idx % (BN / 4);
                ((float4*)&Ws[nxt][wr][0])[wc] = wreg[i];
            }
            __syncthreads();
        }
    }

    float bv[NJ * 4];
#pragma unroll
    for (int jv = 0; jv < NJ; jv++)
#pragma unroll
        for (int k = 0; k < 4; k++) bv[jv * 4 + k] = bias[jv * 64 + tx * 4 + k];
#pragma unroll
    for (int u = 0; u < 4; u++) {
        int row = n0 + ty * 4 + u;
        if (row < M) {
#pragma unroll
            for (int jv = 0; jv < NJ; jv++) {
                float v0, v1, v2, v3;
                UNPACK2(v0, v1, acc[u][jv * 2 + 0]);
                UNPACK2(v2, v3, acc[u][jv * 2 + 1]);
                *(float4*)(C + (size_t)row * BN + jv * 64 + tx * 4) =
                    make_float4(v0 + bv[jv * 4 + 0], v1 + bv[jv * 4 + 1],
                                v2 + bv[jv * 4 + 2], v3 + bv[jv * 4 + 3]);
            }
        }
    }
}

// closed-form exp(A) for A in so(4), via self-dual split
__device__ __forceinline__ void expm_so4(const float* ms, float* T) {
    float a12 = ms[1] - ms[4];
    float a13 = ms[2] - ms[8];
    float a14 = ms[3] - ms[12];
    float a23 = ms[6] - ms[9];
    float a24 = ms[7] - ms[13];
    float a34 = ms[11] - ms[14];

    float p1 = 0.5f * (a12 + a34), p2 = 0.5f * (a13 - a24), p3 = 0.5f * (a14 + a23);
    float q1 = 0.5f * (a12 - a34), q2 = 0.5f * (a13 + a24), q3 = 0.5f * (a14 - a23);

    float tp2 = p1 * p1 + p2 * p2 + p3 * p3;
    float tq2 = q1 * q1 + q2 * q2 + q3 * q3;
    float tp = sqrtf(tp2), tq = sqrtf(tq2);
    float svp, cvp, svq, cvq;
    __sincosf(tp, &svp, &cvp);
    __sincosf(tq, &svq, &cvq);
    float sp = (tp2 > 1e-12f) ? svp / tp : 1.0f - tp2 * (1.0f / 6.0f);
    float sq = (tq2 > 1e-12f) ? svq / tq : 1.0f - tq2 * (1.0f / 6.0f);

    float Ap[16] = {0.f,  p1,  p2,  p3,
                    -p1, 0.f,  p3, -p2,
                    -p2, -p3, 0.f,  p1,
                    -p3,  p2, -p1, 0.f};
    float Aq[16] = {0.f,  q1,  q2,  q3,
                    -q1, 0.f, -q3,  q2,
                    -q2,  q3, 0.f, -q1,
                    -q3, -q2,  q1, 0.f};
    float B[16];
#pragma unroll
    for (int a = 0; a < 4; a++)
#pragma unroll
        for (int b = 0; b < 4; b++)
            B[a * 4 + b] = Ap[a * 4 + 0] * Aq[0 * 4 + b] + Ap[a * 4 + 1] * Aq[1 * 4 + b] +
                           Ap[a * 4 + 2] * Aq[2 * 4 + b] + Ap[a * 4 + 3] * Aq[3 * 4 + b];

    float cc = cvp * cvq, scp = sp * cvq, csq = cvp * sq, ssv = sp * sq;
#pragma unroll
    for (int j = 0; j < 16; j++)
        T[j] = ((j % 5 == 0) ? cc : 0.0f) + scp * Ap[j] + csq * Aq[j] + ssv * B[j];
}

// ---------------- fused edge kernel ----------------
// Phase 1 (thread per edge): MLP2 (f32x2) + 2x closed-form expm; R = T_u^T T_v -> SHARED.
// Phase 2 (warp per edge x32): m = R @ x_j(=h[row]); red.global.add.v4 into agg[col].
// (uses f_u orthogonal: msg = x_i - R x_j; the x_i part is folded into update via deg.)
__global__ __launch_bounds__(256) void edge_fused_kernel(const float* __restrict__ h,
                                                         const int* __restrict__ ei,
                                                         const float* __restrict__ w2,
                                                         const float* __restrict__ b2) {
    __shared__ __align__(16) ulonglong2 w2s[512];   // [64 inputs][32 outputs]
    __shared__ __align__(16) u64 b2s[16];
    __shared__ __align__(16) float Rs[256 * 16];    // per local edge: R = f_u^T f_v
    __shared__ int rs[256], cs[256];

    for (int idx = threadIdx.x; idx < 512; idx += 256) w2s[idx] = ((const ulonglong2*)w2)[idx];
    if (threadIdx.x < 16) b2s[threadIdx.x] = ((const u64*)b2)[threadIdx.x];

    const int tid = threadIdx.x;
    const int e = blockIdx.x * 256 + tid;   // grid = EE/256
    const int r = clamp_idx(ei[e]);
    const int c = clamp_idx(ei[EE + e]);
    rs[tid] = r;
    cs[tid] = c;
    __syncthreads();

    // ---- phase 1: maps ----
    {
        const float4* Pr = (const float4*)(g_PQ + (size_t)r * 128);        // P = first 64
        const float4* Qr = (const float4*)(g_PQ + (size_t)c * 128 + 64);   // Q = last 64

        u64 mm[16];
#pragma unroll
        for (int j = 0; j < 16; j++) mm[j] = b2s[j];

#pragma unroll 4
        for (int i4 = 0; i4 < 16; i4++) {
            float4 p = Pr[i4], q = Qr[i4];
            float hv[4];
            hv[0] = fmaxf(p.x + q.x, 0.0f);
            hv[1] = fmaxf(p.y + q.y, 0.0f);
            hv[2] = fmaxf(p.z + q.z, 0.0f);
            hv[3] = fmaxf(p.w + q.w, 0.0f);
#pragma unroll
            for (int u = 0; u < 4; u++) {
                u64 ph;
                PACK2(ph, hv[u], hv[u]);
                const ulonglong2* wrow = &w2s[(i4 * 4 + u) * 8];
#pragma unroll
                for (int jv = 0; jv < 8; jv++) {
                    ulonglong2 w = wrow[jv];
                    FMA2(mm[jv * 2 + 0], ph, w.x);
                    FMA2(mm[jv * 2 + 1], ph, w.y);
                }
            }
        }

        float m[32];
#pragma unroll
        for (int j = 0; j < 16; j++) UNPACK2(m[2 * j], m[2 * j + 1], mm[j]);

        float Tu[16], Tv[16];
        expm_so4(&m[0], Tu);
        expm_so4(&m[16], Tv);

        // R[a][b] = sum_k Tu[k][a] * Tv[k][b]
        float4* out = (float4*)(Rs + tid * 16);
#pragma unroll
        for (int a = 0; a < 4; a++) {
            float r0 = Tu[0 * 4 + a] * Tv[0] + Tu[1 * 4 + a] * Tv[4] + Tu[2 * 4 + a] * Tv[8]  + Tu[3 * 4 + a] * Tv[12];
            float r1 = Tu[0 * 4 + a] * Tv[1] + Tu[1 * 4 + a] * Tv[5] + Tu[2 * 4 + a] * Tv[9]  + Tu[3 * 4 + a] * Tv[13];
            float r2 = Tu[0 * 4 + a] * Tv[2] + Tu[1 * 4 + a] * Tv[6] + Tu[2 * 4 + a] * Tv[10] + Tu[3 * 4 + a] * Tv[14];
            float r3 = Tu[0 * 4 + a] * Tv[3] + Tu[1 * 4 + a] * Tv[7] + Tu[2 * 4 + a] * Tv[11] + Tu[3 * 4 + a] * Tv[15];
            out[a] = make_float4(r0, r1, r2, r3);
        }
    }
    __syncthreads();

    // ---- phase 2: messages (warp per edge, pipelined xj gather) ----
    const int warp = tid >> 5;
    const int lane = tid & 31;
    const int le0 = warp * 32;

    float4 xj = ((const float4*)(h + (size_t)rs[le0] * 128))[lane];

#pragma unroll 1
    for (int i = 0; i < 32; i++) {
        int le = le0 + i;
        int cc = cs[le];

        float4 nxj;
        if (i < 31) nxj = ((const float4*)(h + (size_t)rs[le + 1] * 128))[lane];

        const float4* Rp = (const float4*)(Rs + le * 16);
        float4 r0 = Rp[0], r1 = Rp[1], r2 = Rp[2], r3 = Rp[3];

        float m0 = r0.x * xj.x + r0.y * xj.y + r0.z * xj.z + r0.w * xj.w;
        float m1 = r1.x * xj.x + r1.y * xj.y + r1.z * xj.z + r1.w * xj.w;
        float m2 = r2.x * xj.x + r2.y * xj.y + r2.z * xj.z + r2.w * xj.w;
        float m3 = r3.x * xj.x + r3.y * xj.y + r3.z * xj.z + r3.w * xj.w;

        float* dst = g_agg + (size_t)cc * 128 + lane * 4;   // 16B aligned
        asm volatile("red.global.add.v4.f32 [%0], {%1, %2, %3, %4};"
                     :: "l"(dst), "f"(m0), "f"(m1), "f"(m2), "f"(m3) : "memory");

        xj = nxj;
    }
}

// ---------------- update: hout = elu(h*(1-eps*deg) + eps*agg), re-zero agg ----------------
__global__ void update_elu_kernel(const float4* __restrict__ hin, float4* __restrict__ hout,
                                  const float* __restrict__ eps) {
    int i = blockIdx.x * 256 + threadIdx.x;
    if (i >= NN * HIDF / 4) return;
    float ev = eps[0];
    float scale = 1.0f - ev * g_deg[i >> 5];    // node = i*4/128
    float4 a = ((const float4*)g_agg)[i];
    float4 hv = hin[i];
    float4 o;
    float v;
    v = hv.x * scale + ev * a.x; o.x = (v > 0.0f) ? v : expm1f(v);
    v = hv.y * scale + ev * a.y; o.y = (v > 0.0f) ? v : expm1f(v);
    v = hv.z * scale + ev * a.z; o.z = (v > 0.0f) ? v : expm1f(v);
    v = hv.w * scale + ev * a.w; o.w = (v > 0.0f) ? v : expm1f(v);
    hout[i] = o;
    ((float4*)g_agg)[i] = make_float4(0.f, 0.f, 0.f, 0.f);
}

// ---------------- launch ----------------
extern "C" void kernel_launch(void* const* d_in, const int* in_sizes, int n_in,
                              void* d_out, int out_size) {
    const float* x         = (const float*)d_in[0];
    const int* ei          = (const int*)d_in[1];
    const float* lin_in_w  = (const float*)d_in[2];
    const float* lin_in_b  = (const float*)d_in[3];
    const float* c0_w1     = (const float*)d_in[4];
    const float* c0_b1     = (const float*)d_in[5];
    const float* c0_w2     = (const float*)d_in[6];
    const float* c0_b2     = (const float*)d_in[7];
    const float* c0_eps    = (const float*)d_in[8];
    const float* c1_w1     = (const float*)d_in[9];
    const float* c1_b1     = (const float*)d_in[10];
    const float* c1_w2     = (const float*)d_in[11];
    const float* c1_b2     = (const float*)d_in[12];
    const float* c1_eps    = (const float*)d_in[13];
    const float* lin_out_w = (const float*)d_in[14];
    const float* lin_out_b = (const float*)d_in[15];
    float* out = (float*)d_out;

    float* hA;  cudaGetSymbolAddress((void**)&hA, g_hA);
    float* hB;  cudaGetSymbolAddress((void**)&hB, g_hB);
    float* PQ;  cudaGetSymbolAddress((void**)&PQ, g_PQ);
    float* wpq; cudaGetSymbolAddress((void**)&wpq, g_wpq);
    float* bpq; cudaGetSymbolAddress((void**)&bpq, g_bpq);

    const int gemmBlocks = (NN + 63) / 64;         // 313
    const int edgeBlocks = EE / 256;               // 1250
    const int vecBlocks  = (NN * HIDF / 4) / 256;  // 2500

    zero_agg_kernel<<<vecBlocks, 256>>>();
    deg_kernel<<<edgeBlocks, 256>>>(ei);

    // h = x @ Win + b
    gemm_kernel<128><<<gemmBlocks, 256>>>(x, lin_in_w, lin_in_b, hA, NN);

    // ---- conv0: hA -> hB ----
    repack_w1_kernel<<<128, 128>>>(c0_w1, c0_b1);
    gemm_kernel<128><<<gemmBlocks, 256>>>(hA, wpq, bpq, PQ, NN);
    edge_fused_kernel<<<edgeBlocks, 256>>>(hA, ei, c0_w2, c0_b2);
    update_elu_kernel<<<vecBlocks, 256>>>((const float4*)hA, (float4*)hB, c0_eps);

    // ---- conv1: hB -> hA ----
    repack_w1_kernel<<<128, 128>>>(c1_w1, c1_b1);
    gemm_kernel<128><<<gemmBlocks, 256>>>(hB, wpq, bpq, PQ, NN);
    edge_fused_kernel<<<edgeBlocks, 256>>>(hB, ei, c1_w2, c1_b2);
    update_elu_kernel<<<vecBlocks, 256>>>((const float4*)hB, (float4*)hA, c1_eps);

    // out = hA @ Wout + bout
    gemm_kernel<64><<<gemmBlocks, 256>>>(hA, lin_out_w, lin_out_b, out, NN);
}